// round 8
// baseline (speedup 1.0000x reference)
#include <cuda_runtime.h>

// Problem shape (fixed by dataset): source [B,N,3], target [B,M,3], fp32.
#define Bq 2
#define Nq 8192
#define Mq 8192
#define BN (Bq * Nq)                 // 16384 sources

// Spatial grid: exact 1-NN with ring pruning. Domain [-3,3]^3, 32^3 cells.
#define G 32
#define CELLS (G * G * G)            // 32768
#define DOM_LO (-3.0f)
#define Hc (6.0f / 32.0f)            // 0.1875
#define INV_H (32.0f / 6.0f)

#define TB 1024                      // build threads (1 block per batch)
#define TS 256                       // search threads per block
#define LPS 8                        // lanes per source (coalesced gathers)
#define NBLK_S (BN * LPS / TS)       // 512 search blocks

// Scratch (no device allocations allowed). All arrays are fully rewritten
// each run (replay-safe); g_ticket self-resets.
__device__ int    g_cnt[Bq][CELLS];
__device__ int    g_cellstart[Bq][CELLS + 1];
__device__ int    g_cur[Bq][CELLS];
__device__ int    g_cellid[Bq][Mq];
__device__ float4 g_sorted[Bq][Mq];
__device__ float  g_blocksum[NBLK_S];
__device__ int    g_ticket;

__device__ __forceinline__ int cell_of(float v) {
    int c = __float2int_rd((v - DOM_LO) * INV_H);
    return min(G - 1, max(0, c));
}

// Kernel 1: per-batch CSR grid build. One block per batch.
__global__ __launch_bounds__(TB) void build_kernel(const float* __restrict__ tgt) {
    const int b = blockIdx.x;
    const int tid = threadIdx.x;

    // 1. zero counts
    for (int i = tid; i < CELLS; i += TB) g_cnt[b][i] = 0;
    __syncthreads();

    // 2. histogram + remember cell ids
    for (int i = tid; i < Mq; i += TB) {
        const float* p = tgt + (b * Mq + i) * 3;
        int cell = (cell_of(p[0]) * G + cell_of(p[1])) * G + cell_of(p[2]);
        g_cellid[b][i] = cell;
        atomicAdd(&g_cnt[b][cell], 1);
    }
    __syncthreads();

    // 3. exclusive scan over 32768 cells: 32 cells/thread + block scan.
    __shared__ int sp[TB];
    const int base = tid * (CELLS / TB);
    int local[CELLS / TB];
    int sum = 0;
#pragma unroll
    for (int k = 0; k < CELLS / TB; k++) {
        local[k] = g_cnt[b][base + k];
        sum += local[k];
    }
    sp[tid] = sum;
    __syncthreads();
    for (int off = 1; off < TB; off <<= 1) {        // Hillis-Steele inclusive
        int v = (tid >= off) ? sp[tid - off] : 0;
        __syncthreads();
        sp[tid] += v;
        __syncthreads();
    }
    int run = sp[tid] - sum;                        // exclusive prefix
#pragma unroll
    for (int k = 0; k < CELLS / TB; k++) {
        g_cellstart[b][base + k] = run;
        g_cur[b][base + k] = run;
        run += local[k];
    }
    if (tid == TB - 1) g_cellstart[b][CELLS] = run; // == Mq
    __syncthreads();

    // 4. scatter targets (order within a cell is atomic-dependent, but the
    //    exact min over a cell is order-independent -> deterministic result).
    for (int i = tid; i < Mq; i += TB) {
        const float* p = tgt + (b * Mq + i) * 3;
        int pos = atomicAdd(&g_cur[b][g_cellid[b][i]], 1);
        g_sorted[b][pos] = make_float4(p[0], p[1], p[2], 0.0f);
    }
}

// Kernel 2: exact NN search. 8 lanes cooperate per source (strided candidates
// -> coalesced float4 gathers). Rings: scan cube radius 1 (27 cells), stop if
// best <= (K*h)^2 (ring K+1 has min distance >= K*h, bound survives cell
// clamping); rare expansion is warp-uniform via __any_sync. Tail: fixed-tree
// block sums + ticketed last block -> deterministic mean.
__global__ __launch_bounds__(TS) void search_kernel(const float* __restrict__ src,
                                                    float* __restrict__ out) {
    __shared__ float sred[TS];
    __shared__ bool is_last;

    const int tid = threadIdx.x;
    const int gthread = blockIdx.x * TS + tid;
    const int si = gthread >> 3;                    // source index
    const int lane = tid & (LPS - 1);
    const int b = si >> 13;                         // / Nq
    const int n = si & (Nq - 1);

    const float sx = src[si * 3 + 0];
    const float sy = src[si * 3 + 1];
    const float sz = src[si * 3 + 2];
    const int cx = cell_of(sx), cy = cell_of(sy), cz = cell_of(sz);

    const float4* __restrict__ ts = g_sorted[b];
    const int* __restrict__ cs = g_cellstart[b];

    float best = __int_as_float(0x7f800000);

    // Rings 0-1: cube radius 1, z-runs contiguous.
#pragma unroll
    for (int dx = -1; dx <= 1; dx++) {
        int x = cx + dx;
        if (x < 0 || x >= G) continue;
#pragma unroll
        for (int dy = -1; dy <= 1; dy++) {
            int y = cy + dy;
            if (y < 0 || y >= G) continue;
            int zb = (x * G + y) * G;
            int zlo = max(cz - 1, 0), zhi = min(cz + 1, G - 1);
            int s0 = __ldg(&cs[zb + zlo]);
            int s1 = __ldg(&cs[zb + zhi + 1]);
            for (int i = s0 + lane; i < s1; i += LPS) {
                float4 t = __ldg(&ts[i]);
                float ddx = sx - t.x, ddy = sy - t.y, ddz = sz - t.z;
                float d2 = fmaf(ddx, ddx, fmaf(ddy, ddy, ddz * ddz));
                best = fminf(best, d2);
            }
        }
    }
    // group min (xor stays within the 8-lane group)
#pragma unroll
    for (int m = 1; m < LPS; m <<= 1)
        best = fminf(best, __shfl_xor_sync(0xFFFFFFFFu, best, m));

    // Rare ring expansion, warp-uniform iteration.
    int K = 1;
    while (true) {
        bool active = (best > (float)K * Hc * ((float)K * Hc)) && (K < G);
        if (!__any_sync(0xFFFFFFFFu, active)) break;
        if (active) {
            K++;
            for (int dx = -K; dx <= K; dx++) {
                int x = cx + dx;
                if (x < 0 || x >= G) continue;
                for (int dy = -K; dy <= K; dy++) {
                    int y = cy + dy;
                    if (y < 0 || y >= G) continue;
                    int zb = (x * G + y) * G;
                    bool edge = (dx == -K || dx == K || dy == -K || dy == K);
                    int r0lo, r0hi, r1lo, r1hi;
                    if (edge) {           // full z run
                        r0lo = max(cz - K, 0); r0hi = min(cz + K, G - 1);
                        r1lo = 1; r1hi = 0;   // empty
                    } else {              // just the two z caps
                        r0lo = cz - K; r0hi = cz - K;
                        r1lo = cz + K; r1hi = cz + K;
                        if (r0lo < 0) { r0lo = 1; r0hi = 0; }
                        if (r1hi >= G) { r1lo = 1; r1hi = 0; }
                    }
                    for (int pass = 0; pass < 2; pass++) {
                        int lo = pass ? r1lo : r0lo, hi = pass ? r1hi : r0hi;
                        if (lo > hi) continue;
                        int s0 = __ldg(&cs[zb + lo]);
                        int s1 = __ldg(&cs[zb + hi + 1]);
                        for (int i = s0 + lane; i < s1; i += LPS) {
                            float4 t = __ldg(&ts[i]);
                            float ddx = sx - t.x, ddy = sy - t.y, ddz = sz - t.z;
                            float d2 = fmaf(ddx, ddx, fmaf(ddy, ddy, ddz * ddz));
                            best = fminf(best, d2);
                        }
                    }
                }
            }
        }
#pragma unroll
        for (int m = 1; m < LPS; m <<= 1)
            best = fminf(best, __shfl_xor_sync(0xFFFFFFFFu, best, m));
    }
    (void)n;

    // Block sum (fixed tree over 32 per-source values).
    if (lane == 0) sred[tid >> 3] = best;
    __syncthreads();
    if (tid < 16) sred[tid] += sred[tid + 16];
    __syncthreads();
    if (tid < 8) sred[tid] += sred[tid + 8];
    __syncthreads();
    if (tid < 4) sred[tid] += sred[tid + 4];
    __syncthreads();
    if (tid < 2) sred[tid] += sred[tid + 2];
    __syncthreads();
    if (tid == 0) g_blocksum[blockIdx.x] = sred[0] + sred[1];

    // Ticket: last block reduces all block sums in fixed order.
    __threadfence();
    __syncthreads();
    if (tid == 0) {
        int t = atomicAdd(&g_ticket, 1);
        is_last = (t == NBLK_S - 1);
    }
    __syncthreads();
    if (!is_last) return;

    __threadfence();
    float acc = __ldcg(&g_blocksum[tid]) + __ldcg(&g_blocksum[tid + TS]);
    sred[tid] = acc;
    __syncthreads();
#pragma unroll
    for (int o = TS / 2; o > 0; o >>= 1) {
        if (tid < o) sred[tid] += sred[tid + o];
        __syncthreads();
    }
    if (tid == 0) {
        out[0] = sred[0] * (1.0f / (float)(BN * 3));
        g_ticket = 0;                               // reset for next replay
    }
}

extern "C" void kernel_launch(void* const* d_in, const int* in_sizes, int n_in,
                              void* d_out, int out_size) {
    const float* src = (const float*)d_in[0];   // source_point_cloud [B,N,3]
    const float* tgt = (const float*)d_in[1];   // target_point_cloud [B,M,3]
    (void)in_sizes; (void)n_in; (void)out_size;

    build_kernel<<<Bq, TB>>>(tgt);
    search_kernel<<<NBLK_S, TS>>>(src, (float*)d_out);
}

// round 9
// speedup vs baseline: 3.5105x; 3.5105x over previous
#include <cuda_runtime.h>

// Problem shape (fixed by dataset): source [B,N,3], target [B,M,3], fp32.
#define Bq 2
#define Nq 8192
#define Mq 8192
#define BN (Bq * Nq)                 // 16384 sources
#define BM (Bq * Mq)                 // 16384 targets

// Spatial grid: exact 1-NN. Domain [-3,3]^3, 16^3 cells (h=0.375).
// Cells clamp, so edge cells extend to +-inf -> exactness preserved.
#define G 16
#define CELLS (G * G * G)            // 4096
#define DOM_LO (-3.0f)
#define Hc (6.0f / 16.0f)            // 0.375
#define INV_H (16.0f / 6.0f)

#define TBB 256                      // build threads
#define NBB 32                       // build blocks (co-resident, spin barriers)
#define TS 256                       // search threads (8 warps = 8 sources/block)
#define NBLK_S (BN / 8)              // 2048 search blocks

// Scratch (no device allocations). All state is either rewritten each run or
// explicitly self-reset (g_cnt by scan phase, barriers by last arriver,
// g_ticket by tail block) -> graph-replay safe.
__device__ int      g_cnt[Bq][CELLS];         // zero-init; reset each run
__device__ int      g_cellstart[Bq][CELLS + 1];
__device__ int      g_cur[Bq][CELLS];
__device__ int      g_cellid[BM];
__device__ float4   g_sorted[Bq][Mq];
__device__ float    g_blocksum[NBLK_S];
__device__ unsigned g_barA, g_barB, g_barC;   // zero-init; self-reset
__device__ int      g_ticket;                 // zero-init; self-reset

__device__ __forceinline__ int cell_of(float v) {
    int c = __float2int_rd((v - DOM_LO) * INV_H);
    return min(G - 1, max(0, c));
}

__device__ __forceinline__ void grid_barrier(unsigned* bar) {
    __syncthreads();
    if (threadIdx.x == 0) {
        __threadfence();
        atomicAdd(bar, 1u);
        while (atomicAdd(bar, 0u) < NBB) { }
    }
    __syncthreads();
    __threadfence();
}

// Kernel 1: fused grid build (histogram -> scan -> scatter) across 32
// co-resident blocks with spin barriers. Scatter order within a cell is
// atomic-dependent, but min over a cell is order-independent -> deterministic.
__global__ __launch_bounds__(TBB) void build_kernel(const float* __restrict__ tgt) {
    const int tid = threadIdx.x;
    const int gt = blockIdx.x * TBB + tid;

    // Phase 1: histogram (+ remember cell ids). g_cnt is zero on entry.
    for (int i = gt; i < BM; i += NBB * TBB) {
        const float* p = tgt + i * 3;
        int b = i >> 13;
        int cell = (cell_of(p[0]) * G + cell_of(p[1])) * G + cell_of(p[2]);
        g_cellid[i] = cell;
        atomicAdd(&g_cnt[b][cell], 1);
    }
    grid_barrier(&g_barA);

    // Phase 2: exclusive scan (blocks 0,1 only; 16 cells/thread + block scan).
    if (blockIdx.x < Bq) {
        const int b = blockIdx.x;
        __shared__ int wsum[TBB / 32];
        const int base = tid * (CELLS / TBB);
        int loc[CELLS / TBB];
        int s = 0;
#pragma unroll
        for (int k = 0; k < CELLS / TBB; k++) { loc[k] = g_cnt[b][base + k]; s += loc[k]; }
        int lane = tid & 31, wid = tid >> 5;
        int incl = s;
#pragma unroll
        for (int o = 1; o < 32; o <<= 1) {
            int v = __shfl_up_sync(0xFFFFFFFFu, incl, o);
            if (lane >= o) incl += v;
        }
        if (lane == 31) wsum[wid] = incl;
        __syncthreads();
        if (tid < TBB / 32) {
            int v = wsum[tid], inc = v;
#pragma unroll
            for (int o = 1; o < TBB / 32; o <<= 1) {
                int t = __shfl_up_sync(0xFFu, inc, o);
                if (tid >= o) inc += t;
            }
            wsum[tid] = inc - v;                    // exclusive warp offsets
        }
        __syncthreads();
        int run = wsum[wid] + (incl - s);           // block-exclusive prefix
#pragma unroll
        for (int k = 0; k < CELLS / TBB; k++) {
            g_cellstart[b][base + k] = run;
            g_cur[b][base + k] = run;
            g_cnt[b][base + k] = 0;                 // reset for next replay
            run += loc[k];
        }
        if (tid == TBB - 1) g_cellstart[b][CELLS] = run;   // == Mq
    }
    grid_barrier(&g_barB);

    // Phase 3: scatter targets into CSR order.
    for (int i = gt; i < BM; i += NBB * TBB) {
        const float* p = tgt + i * 3;
        int b = i >> 13;
        int pos = atomicAdd(&g_cur[b][g_cellid[i]], 1);
        g_sorted[b][pos] = make_float4(p[0], p[1], p[2], 0.0f);
    }

    // Arrive-only final barrier: last arriver resets the barrier counters.
    __syncthreads();
    if (tid == 0) {
        __threadfence();
        unsigned t = atomicAdd(&g_barC, 1u);
        if (t == NBB - 1) { g_barA = 0; g_barB = 0; g_barC = 0; }
    }
}

// Min distance from s to the boundary of the scanned cube (radius K around
// (cx,cy,cz), clamped). Clamped faces cover to +-inf -> excluded (1e30).
__device__ __forceinline__ float slab_bound(float sx, float sy, float sz,
                                            int cx, int cy, int cz, int K) {
    float d = 1e30f;
    int lo, hi;
    lo = cx - K; hi = cx + K;
    if (lo > 0)     d = fminf(d, sx - (DOM_LO + lo * Hc));
    if (hi < G - 1) d = fminf(d, (DOM_LO + (hi + 1) * Hc) - sx);
    lo = cy - K; hi = cy + K;
    if (lo > 0)     d = fminf(d, sy - (DOM_LO + lo * Hc));
    if (hi < G - 1) d = fminf(d, (DOM_LO + (hi + 1) * Hc) - sy);
    lo = cz - K; hi = cz + K;
    if (lo > 0)     d = fminf(d, sz - (DOM_LO + lo * Hc));
    if (hi < G - 1) d = fminf(d, (DOM_LO + (hi + 1) * Hc) - sz);
    return d;
}

// Kernel 2: exact NN search, ONE WARP PER SOURCE. All 18 run bounds loaded
// as independent uniform LDGs, then all 9 column gathers issued into regs
// before consumption (MLP ~9-18) -> ~2 L2 round-trips per source. Stop when
// best <= slab_bound^2 (exact). Rare ring expansion is per-warp uniform.
__global__ __launch_bounds__(TS) void search_kernel(const float* __restrict__ src,
                                                    float* __restrict__ out) {
    __shared__ float sred[TS / 32];
    __shared__ bool is_last;

    const int tid = threadIdx.x;
    const int lane = tid & 31;
    const int si = blockIdx.x * (TS / 32) + (tid >> 5);   // source index
    const int b = si >> 13;

    const float sx = __ldg(&src[si * 3 + 0]);
    const float sy = __ldg(&src[si * 3 + 1]);
    const float sz = __ldg(&src[si * 3 + 2]);
    const int cx = cell_of(sx), cy = cell_of(sy), cz = cell_of(sz);

    const float4* __restrict__ ts = g_sorted[b];
    const int* __restrict__ cs = g_cellstart[b];

    const int zlo = max(cz - 1, 0), zhi = min(cz + 1, G - 1);

    // Phase A: 18 independent run-bound loads (uniform addresses).
    int s0[9], s1[9];
#pragma unroll
    for (int j = 0; j < 9; j++) {
        int x = cx + j / 3 - 1, y = cy + j % 3 - 1;
        bool valid = (x >= 0) && (x < G) && (y >= 0) && (y < G);
        int zb = (x * G + y) * G;
        s0[j] = valid ? __ldg(&cs[zb + zlo]) : 0;
        s1[j] = valid ? __ldg(&cs[zb + zhi + 1]) : 0;
    }

    // Phase B: issue all 9 column gathers before consuming (register MLP).
    float best = 1e30f;
    float4 cand[9];
    bool has[9];
#pragma unroll
    for (int j = 0; j < 9; j++) {
        int idx = s0[j] + lane;
        has[j] = idx < s1[j];
        cand[j] = has[j] ? __ldg(&ts[idx]) : make_float4(1e15f, 1e15f, 1e15f, 0.f);
    }
#pragma unroll
    for (int j = 0; j < 9; j++) {
        float dx = sx - cand[j].x, dy = sy - cand[j].y, dz = sz - cand[j].z;
        float d2 = fmaf(dx, dx, fmaf(dy, dy, dz * dz));
        best = fminf(best, d2);
    }
    // Rare: column longer than 32 candidates.
#pragma unroll
    for (int j = 0; j < 9; j++) {
        for (int i = s0[j] + 32 + lane; i < s1[j]; i += 32) {
            float4 t = __ldg(&ts[i]);
            float dx = sx - t.x, dy = sy - t.y, dz = sz - t.z;
            best = fminf(best, fmaf(dx, dx, fmaf(dy, dy, dz * dz)));
        }
    }
#pragma unroll
    for (int m = 16; m > 0; m >>= 1)
        best = fminf(best, __shfl_xor_sync(0xFFFFFFFFu, best, m));

    // Exact stop test; rare per-warp ring expansion (~1% of sources at G=16).
    int K = 1;
    float bnd = slab_bound(sx, sy, sz, cx, cy, cz, K);
    while (best > bnd * bnd && K < G) {
        K++;
        int xl = max(cx - K, 0), xh = min(cx + K, G - 1);
        int yl = max(cy - K, 0), yh = min(cy + K, G - 1);
        int zl = max(cz - K, 0), zh = min(cz + K, G - 1);
        for (int x = xl; x <= xh; x++)
            for (int y = yl; y <= yh; y++) {
                int zb = (x * G + y) * G;
                int a = __ldg(&cs[zb + zl]);
                int e = __ldg(&cs[zb + zh + 1]);
                for (int i = a + lane; i < e; i += 32) {
                    float4 t = __ldg(&ts[i]);
                    float dx = sx - t.x, dy = sy - t.y, dz = sz - t.z;
                    best = fminf(best, fmaf(dx, dx, fmaf(dy, dy, dz * dz)));
                }
            }
#pragma unroll
        for (int m = 16; m > 0; m >>= 1)
            best = fminf(best, __shfl_xor_sync(0xFFFFFFFFu, best, m));
        bnd = slab_bound(sx, sy, sz, cx, cy, cz, K);
    }

    // Per-block fixed-order sum of the 8 per-source bests.
    if (lane == 0) sred[tid >> 5] = best;
    __syncthreads();
    if (tid == 0) {
        float s = 0.f;
#pragma unroll
        for (int w = 0; w < TS / 32; w++) s += sred[w];
        g_blocksum[blockIdx.x] = s;
    }

    // Ticketed last block: fixed-order global sum -> mean.
    __threadfence();
    __syncthreads();
    if (tid == 0) {
        int t = atomicAdd(&g_ticket, 1);
        is_last = (t == NBLK_S - 1);
    }
    __syncthreads();
    if (!is_last) return;

    __threadfence();
    __shared__ float fred[TS];
    float acc = 0.f;
#pragma unroll
    for (int k = 0; k < NBLK_S / TS; k++)
        acc += __ldcg(&g_blocksum[k * TS + tid]);
    fred[tid] = acc;
    __syncthreads();
#pragma unroll
    for (int o = TS / 2; o > 0; o >>= 1) {
        if (tid < o) fred[tid] += fred[tid + o];
        __syncthreads();
    }
    if (tid == 0) {
        out[0] = fred[0] * (1.0f / (float)(BN * 3));
        g_ticket = 0;                               // reset for next replay
    }
}

extern "C" void kernel_launch(void* const* d_in, const int* in_sizes, int n_in,
                              void* d_out, int out_size) {
    const float* src = (const float*)d_in[0];   // source_point_cloud [B,N,3]
    const float* tgt = (const float*)d_in[1];   // target_point_cloud [B,M,3]
    (void)in_sizes; (void)n_in; (void)out_size;

    build_kernel<<<NBB, TBB>>>(tgt);
    search_kernel<<<NBLK_S, TS>>>(src, (float*)d_out);
}

// round 10
// speedup vs baseline: 6.2107x; 1.7692x over previous
#include <cuda_runtime.h>

// Problem shape (fixed by dataset): source [B,N,3], target [B,M,3], fp32.
#define Bq 2
#define Nq 8192
#define Mq 8192
#define BN (Bq * Nq)                 // 16384 sources
#define BM (Bq * Mq)                 // 16384 targets

// Spatial grid: exact 1-NN. Domain [-3,3]^3, 16^3 cells (h=0.375).
// Cells clamp, so edge cells extend to +-inf -> exactness preserved.
#define G 16
#define CELLS (G * G * G)            // 4096
#define DOM_LO (-3.0f)
#define Hc (6.0f / 16.0f)            // 0.375
#define INV_H (16.0f / 6.0f)

#define THIST 256
#define TSCAN 256
#define TS 256                       // search threads (8 warps = 8 sources/block)
#define NBLK_S (BN / 8)              // 2048 search blocks

// Scratch (no device allocations). g_cnt is zero on entry to hist (zero-init
// on load; reset by the scan kernel each run) -> graph-replay safe.
// g_ticket self-resets in the tail block.
__device__ int    g_cnt[Bq][CELLS];
__device__ int    g_cellstart[Bq][CELLS + 1];
__device__ int    g_cur[Bq][CELLS];
__device__ int    g_cellid[BM];
__device__ float4 g_sorted[Bq][Mq];
__device__ float  g_blocksum[NBLK_S];
__device__ int    g_ticket;

__device__ __forceinline__ int cell_of(float v) {
    int c = __float2int_rd((v - DOM_LO) * INV_H);
    return min(G - 1, max(0, c));
}

// Kernel 1: histogram (+ remember cell ids). Requires g_cnt == 0 on entry.
__global__ __launch_bounds__(THIST) void hist_kernel(const float* __restrict__ tgt) {
    int i = blockIdx.x * THIST + threadIdx.x;
    if (i >= BM) return;
    const float* p = tgt + i * 3;
    int b = i >> 13;
    int cell = (cell_of(p[0]) * G + cell_of(p[1])) * G + cell_of(p[2]);
    g_cellid[i] = cell;
    atomicAdd(&g_cnt[b][cell], 1);
}

// Kernel 2: per-batch exclusive scan (one block per batch; 16 cells/thread),
// writes cellstart + cur, and RESETS g_cnt to zero for the next replay.
__global__ __launch_bounds__(TSCAN) void scan_kernel() {
    const int b = blockIdx.x;
    const int tid = threadIdx.x;
    __shared__ int wsum[TSCAN / 32];
    const int base = tid * (CELLS / TSCAN);
    int loc[CELLS / TSCAN];
    int s = 0;
#pragma unroll
    for (int k = 0; k < CELLS / TSCAN; k++) { loc[k] = g_cnt[b][base + k]; s += loc[k]; }
    int lane = tid & 31, wid = tid >> 5;
    int incl = s;
#pragma unroll
    for (int o = 1; o < 32; o <<= 1) {
        int v = __shfl_up_sync(0xFFFFFFFFu, incl, o);
        if (lane >= o) incl += v;
    }
    if (lane == 31) wsum[wid] = incl;
    __syncthreads();
    if (tid < TSCAN / 32) {
        int v = wsum[tid], inc = v;
#pragma unroll
        for (int o = 1; o < TSCAN / 32; o <<= 1) {
            int t = __shfl_up_sync(0xFFu, inc, o);
            if (tid >= o) inc += t;
        }
        wsum[tid] = inc - v;                        // exclusive warp offsets
    }
    __syncthreads();
    int run = wsum[wid] + (incl - s);               // block-exclusive prefix
#pragma unroll
    for (int k = 0; k < CELLS / TSCAN; k++) {
        g_cellstart[b][base + k] = run;
        g_cur[b][base + k] = run;
        g_cnt[b][base + k] = 0;                     // reset for next replay
        run += loc[k];
    }
    if (tid == TSCAN - 1) g_cellstart[b][CELLS] = run;   // == Mq
}

// Kernel 3: scatter targets into CSR order. Order within a cell is
// atomic-dependent, but min over a cell is order-independent -> deterministic.
__global__ __launch_bounds__(THIST) void scatter_kernel(const float* __restrict__ tgt) {
    int i = blockIdx.x * THIST + threadIdx.x;
    if (i >= BM) return;
    const float* p = tgt + i * 3;
    int b = i >> 13;
    int pos = atomicAdd(&g_cur[b][g_cellid[i]], 1);
    g_sorted[b][pos] = make_float4(p[0], p[1], p[2], 0.0f);
}

// Min distance from s to the boundary of the scanned cube (radius K, clamped).
// Clamped faces cover to +-inf -> excluded (1e30).
__device__ __forceinline__ float slab_bound(float sx, float sy, float sz,
                                            int cx, int cy, int cz, int K) {
    float d = 1e30f;
    int lo, hi;
    lo = cx - K; hi = cx + K;
    if (lo > 0)     d = fminf(d, sx - (DOM_LO + lo * Hc));
    if (hi < G - 1) d = fminf(d, (DOM_LO + (hi + 1) * Hc) - sx);
    lo = cy - K; hi = cy + K;
    if (lo > 0)     d = fminf(d, sy - (DOM_LO + lo * Hc));
    if (hi < G - 1) d = fminf(d, (DOM_LO + (hi + 1) * Hc) - sy);
    lo = cz - K; hi = cz + K;
    if (lo > 0)     d = fminf(d, sz - (DOM_LO + lo * Hc));
    if (hi < G - 1) d = fminf(d, (DOM_LO + (hi + 1) * Hc) - sz);
    return d;
}

// Kernel 4: exact NN search, one warp per source. Common path: 18 parallel
// bound loads + 9 batched column gathers (~2 L2 round-trips). Stop when
// best <= slab_bound(K)^2 (exact). Expansion (rare; only locally-sparse
// sources) rescans the clamped radius-K cube with columns DISTRIBUTED ACROSS
// LANES -> ~2 round-trips per ring instead of a serial column chain.
__global__ __launch_bounds__(TS) void search_kernel(const float* __restrict__ src,
                                                    float* __restrict__ out) {
    __shared__ float sred[TS / 32];
    __shared__ bool is_last;

    const int tid = threadIdx.x;
    const int lane = tid & 31;
    const int si = blockIdx.x * (TS / 32) + (tid >> 5);   // source index
    const int b = si >> 13;

    const float sx = __ldg(&src[si * 3 + 0]);
    const float sy = __ldg(&src[si * 3 + 1]);
    const float sz = __ldg(&src[si * 3 + 2]);
    const int cx = cell_of(sx), cy = cell_of(sy), cz = cell_of(sz);

    const float4* __restrict__ ts = g_sorted[b];
    const int* __restrict__ cs = g_cellstart[b];

    const int zlo = max(cz - 1, 0), zhi = min(cz + 1, G - 1);

    // Phase A: 18 independent run-bound loads (warp-uniform addresses).
    int s0[9], s1[9];
#pragma unroll
    for (int j = 0; j < 9; j++) {
        int x = cx + j / 3 - 1, y = cy + j % 3 - 1;
        bool valid = (x >= 0) && (x < G) && (y >= 0) && (y < G);
        int zb = (x * G + y) * G;
        s0[j] = valid ? __ldg(&cs[zb + zlo]) : 0;
        s1[j] = valid ? __ldg(&cs[zb + zhi + 1]) : 0;
    }

    // Phase B: issue all 9 column gathers before consuming (register MLP).
    float best = 1e30f;
    float4 cand[9];
#pragma unroll
    for (int j = 0; j < 9; j++) {
        int idx = s0[j] + lane;
        cand[j] = (idx < s1[j]) ? __ldg(&ts[idx])
                                : make_float4(1e15f, 1e15f, 1e15f, 0.f);
    }
#pragma unroll
    for (int j = 0; j < 9; j++) {
        float dx = sx - cand[j].x, dy = sy - cand[j].y, dz = sz - cand[j].z;
        best = fminf(best, fmaf(dx, dx, fmaf(dy, dy, dz * dz)));
    }
    // Columns longer than 32 candidates (dense center).
#pragma unroll
    for (int j = 0; j < 9; j++) {
        for (int i = s0[j] + 32 + lane; i < s1[j]; i += 32) {
            float4 t = __ldg(&ts[i]);
            float dx = sx - t.x, dy = sy - t.y, dz = sz - t.z;
            best = fminf(best, fmaf(dx, dx, fmaf(dy, dy, dz * dz)));
        }
    }
#pragma unroll
    for (int m = 16; m > 0; m >>= 1)
        best = fminf(best, __shfl_xor_sync(0xFFFFFFFFu, best, m));

    // Exact stop test; rare lane-parallel ring expansion (warp-uniform branch).
    int K = 1;
    float bnd = slab_bound(sx, sy, sz, cx, cy, cz, K);
    while (best > bnd * bnd && K < G) {
        K++;
        int xl = max(cx - K, 0), xh = min(cx + K, G - 1);
        int yl = max(cy - K, 0), yh = min(cy + K, G - 1);
        int zl = max(cz - K, 0), zh = min(cz + K, G - 1);
        int ny = yh - yl + 1;
        int ncol = (xh - xl + 1) * ny;
        float lb = best;
        for (int j = lane; j < ncol; j += 32) {     // columns across lanes
            int x = xl + j / ny, y = yl + j % ny;
            int zb = (x * G + y) * G;
            int a = __ldg(&cs[zb + zl]);
            int e = __ldg(&cs[zb + zh + 1]);
            for (int i = a; i < e; i++) {           // sparse regions: 0-3 pts
                float4 t = __ldg(&ts[i]);
                float dx = sx - t.x, dy = sy - t.y, dz = sz - t.z;
                lb = fminf(lb, fmaf(dx, dx, fmaf(dy, dy, dz * dz)));
            }
        }
#pragma unroll
        for (int m = 16; m > 0; m >>= 1)
            lb = fminf(lb, __shfl_xor_sync(0xFFFFFFFFu, lb, m));
        best = lb;
        bnd = slab_bound(sx, sy, sz, cx, cy, cz, K);
    }

    // Per-block fixed-order sum of the 8 per-source bests.
    if (lane == 0) sred[tid >> 5] = best;
    __syncthreads();
    if (tid == 0) {
        float s = 0.f;
#pragma unroll
        for (int w = 0; w < TS / 32; w++) s += sred[w];
        g_blocksum[blockIdx.x] = s;
    }

    // Ticketed last block: fixed-order global sum -> mean.
    __threadfence();
    __syncthreads();
    if (tid == 0) {
        int t = atomicAdd(&g_ticket, 1);
        is_last = (t == NBLK_S - 1);
    }
    __syncthreads();
    if (!is_last) return;

    __threadfence();
    __shared__ float fred[TS];
    float acc = 0.f;
#pragma unroll
    for (int k = 0; k < NBLK_S / TS; k++)
        acc += __ldcg(&g_blocksum[k * TS + tid]);
    fred[tid] = acc;
    __syncthreads();
#pragma unroll
    for (int o = TS / 2; o > 0; o >>= 1) {
        if (tid < o) fred[tid] += fred[tid + o];
        __syncthreads();
    }
    if (tid == 0) {
        out[0] = fred[0] * (1.0f / (float)(BN * 3));
        g_ticket = 0;                               // reset for next replay
    }
}

extern "C" void kernel_launch(void* const* d_in, const int* in_sizes, int n_in,
                              void* d_out, int out_size) {
    const float* src = (const float*)d_in[0];   // source_point_cloud [B,N,3]
    const float* tgt = (const float*)d_in[1];   // target_point_cloud [B,M,3]
    (void)in_sizes; (void)n_in; (void)out_size;

    hist_kernel<<<BM / THIST, THIST>>>(tgt);
    scan_kernel<<<Bq, TSCAN>>>();
    scatter_kernel<<<BM / THIST, THIST>>>(tgt);
    search_kernel<<<NBLK_S, TS>>>(src, (float*)d_out);
}